// round 13
// baseline (speedup 1.0000x reference)
#include <cuda_runtime.h>
#include <cuda_fp16.h>
#include <cstdint>

// Shapes (fixed)
constexpr int N_  = 128;
constexpr int L_  = 256;
constexpr int DM  = 256;
constexpr int DP  = 128;

// Device scratch (fp16)
__device__ __half g_A[8192 * 128];   // [(l*32+i)][s]
__device__ __half g_B[8192 * 128];   // [(m*32+j)][s]
__device__ __half g_Wt[DP * 1024];   // [n][ij]

// ---------------------------------------------------------------------------
// helpers
// ---------------------------------------------------------------------------
__device__ __forceinline__ uint32_t smem_u32(const void* p) {
    uint32_t a;
    asm("{ .reg .u64 t; cvta.to.shared.u64 t, %1; cvt.u32.u64 %0, t; }"
        : "=r"(a) : "l"(p));
    return a;
}
__device__ __forceinline__ void ldsm4(uint32_t& r0, uint32_t& r1,
                                      uint32_t& r2, uint32_t& r3, uint32_t a) {
    asm volatile("ldmatrix.sync.aligned.m8n8.x4.shared.b16 {%0,%1,%2,%3}, [%4];"
                 : "=r"(r0), "=r"(r1), "=r"(r2), "=r"(r3) : "r"(a));
}
__device__ __forceinline__ void mma16816(float* d, const uint32_t* a,
                                         uint32_t b0, uint32_t b1) {
    asm volatile(
        "mma.sync.aligned.m16n8k16.row.col.f32.f16.f16.f32 "
        "{%0,%1,%2,%3}, {%4,%5,%6,%7}, {%8,%9}, {%0,%1,%2,%3};"
        : "+f"(d[0]), "+f"(d[1]), "+f"(d[2]), "+f"(d[3])
        : "r"(a[0]), "r"(a[1]), "r"(a[2]), "r"(a[3]), "r"(b0), "r"(b1));
}
__device__ __forceinline__ void cpa16(uint32_t dst, const void* src) {
    asm volatile("cp.async.cg.shared.global [%0], [%1], 16;"
                 :: "r"(dst), "l"(src) : "memory");
}
__device__ __forceinline__ void cpa_commit() {
    asm volatile("cp.async.commit_group;" ::: "memory");
}
template <int N>
__device__ __forceinline__ void cpa_wait() {
    asm volatile("cp.async.wait_group %0;" :: "n"(N) : "memory");
}
__device__ __forceinline__ uint32_t pack2h(float a, float b) {
    __half2 h = __floats2half2_rn(a, b);
    return *(uint32_t*)&h;
}

// ---------------------------------------------------------------------------
// Kernel 1: LN + projections via tensor cores (round-12 version, unchanged).
// ---------------------------------------------------------------------------
constexpr int XST = 264;

__global__ void __launch_bounds__(256) ln_proj_kernel(
    const float* __restrict__ msa,
    const float* __restrict__ gamma,
    const float* __restrict__ beta,
    const float* __restrict__ wl,
    const float* __restrict__ bleft,
    const float* __restrict__ wr,
    const float* __restrict__ bright,
    const float* __restrict__ wo)
{
    extern __shared__ __half sh[];
    __half* Xs = sh;                    // [128][264]
    __half* Wt = sh + 128 * XST;        // [64][264]
    float*  Osm = (float*)sh;           // reuse X region: [64][132]

    int tid = threadIdx.x, lane = tid & 31, w = tid >> 5;
    int l = blockIdx.x;

    // folded wt transpose: this CTA handles 512 of 131072 elements
#pragma unroll
    for (int it = 0; it < 2; it++) {
        int idx = blockIdx.x * 512 + it * 256 + tid;
        int k = idx >> 7, n = idx & 127;
        g_Wt[(size_t)n * 1024 + k] = __float2half_rn(wo[idx]);
    }

    for (int e = tid; e < 8192; e += 256) {
        int d = e >> 5, h = e & 31;
        Wt[h * XST + d]        = __float2half_rn(wl[e]);
        Wt[(h + 32) * XST + d] = __float2half_rn(wr[e]);
    }

    float4 ga0 = *(const float4*)&gamma[lane * 8];
    float4 ga1 = *(const float4*)&gamma[lane * 8 + 4];
    float4 be0 = *(const float4*)&beta[lane * 8];
    float4 be1 = *(const float4*)&beta[lane * 8 + 4];

#pragma unroll 1
    for (int rr4 = 0; rr4 < 4; rr4++) {
        float4 x0[4], x1[4];
#pragma unroll
        for (int r = 0; r < 4; r++) {
            int s = w * 16 + rr4 * 4 + r;
            const float* x = msa + ((size_t)s * L_ + l) * DM;
            x0[r] = *(const float4*)&x[lane * 8];
            x1[r] = *(const float4*)&x[lane * 8 + 4];
        }
#pragma unroll
        for (int r = 0; r < 4; r++) {
            int s = w * 16 + rr4 * 4 + r;
            float sum = x0[r].x + x0[r].y + x0[r].z + x0[r].w
                      + x1[r].x + x1[r].y + x1[r].z + x1[r].w;
            float sq  = x0[r].x*x0[r].x + x0[r].y*x0[r].y + x0[r].z*x0[r].z + x0[r].w*x0[r].w
                      + x1[r].x*x1[r].x + x1[r].y*x1[r].y + x1[r].z*x1[r].z + x1[r].w*x1[r].w;
#pragma unroll
            for (int o = 16; o > 0; o >>= 1) {
                sum += __shfl_xor_sync(0xffffffffu, sum, o);
                sq  += __shfl_xor_sync(0xffffffffu, sq,  o);
            }
            float mu = sum * (1.f / DM);
            float rstd = rsqrtf(sq * (1.f / DM) - mu * mu + 1e-5f);
            uint4 pk;
            pk.x = pack2h((x0[r].x - mu) * rstd * ga0.x + be0.x,
                          (x0[r].y - mu) * rstd * ga0.y + be0.y);
            pk.y = pack2h((x0[r].z - mu) * rstd * ga0.z + be0.z,
                          (x0[r].w - mu) * rstd * ga0.w + be0.w);
            pk.z = pack2h((x1[r].x - mu) * rstd * ga1.x + be1.x,
                          (x1[r].y - mu) * rstd * ga1.y + be1.y);
            pk.w = pack2h((x1[r].z - mu) * rstd * ga1.z + be1.z,
                          (x1[r].w - mu) * rstd * ga1.w + be1.w);
            *(uint4*)&Xs[s * XST + lane * 8] = pk;
        }
    }
    __syncthreads();

    int wm = w >> 1, wn = w & 1;
    float acc[2][4][4];
#pragma unroll
    for (int mt = 0; mt < 2; mt++)
#pragma unroll
        for (int nt = 0; nt < 4; nt++)
#pragma unroll
            for (int q = 0; q < 4; q++) acc[mt][nt][q] = 0.f;

    uint32_t sb = smem_u32(sh);
    uint32_t aAddr = sb + (uint32_t)(((wm * 32 + (lane & 15)) * XST + (lane >> 4) * 8) * 2);
    uint32_t bAddr = sb + (uint32_t)((128 * XST
                    + (wn * 32 + ((lane >> 4) & 1) * 8 + (lane & 7)) * XST
                    + ((lane >> 3) & 1) * 8) * 2);

#pragma unroll
    for (int ks = 0; ks < 16; ks++) {
        uint32_t a[2][4], b[2][4];
#pragma unroll
        for (int mt = 0; mt < 2; mt++)
            ldsm4(a[mt][0], a[mt][1], a[mt][2], a[mt][3],
                  aAddr + (uint32_t)((mt * 16 * XST + ks * 16) * 2));
#pragma unroll
        for (int n2 = 0; n2 < 2; n2++)
            ldsm4(b[n2][0], b[n2][1], b[n2][2], b[n2][3],
                  bAddr + (uint32_t)((n2 * 16 * XST + ks * 16) * 2));
#pragma unroll
        for (int mt = 0; mt < 2; mt++)
#pragma unroll
            for (int nt = 0; nt < 4; nt++)
                mma16816(acc[mt][nt], a[mt],
                         b[nt >> 1][(nt & 1) * 2], b[nt >> 1][(nt & 1) * 2 + 1]);
    }
    __syncthreads();

    {
        int rB = lane >> 2, cB = (lane & 3) * 2;
#pragma unroll
        for (int mt = 0; mt < 2; mt++) {
            int r = wm * 32 + mt * 16 + rB;
#pragma unroll
            for (int nt = 0; nt < 4; nt++) {
                int c = wn * 32 + nt * 8 + cB;
                Osm[c * 132 + r]            = acc[mt][nt][0];
                Osm[(c + 1) * 132 + r]      = acc[mt][nt][1];
                Osm[c * 132 + r + 8]        = acc[mt][nt][2];
                Osm[(c + 1) * 132 + r + 8]  = acc[mt][nt][3];
            }
        }
    }
    __syncthreads();

    {
        int n = tid >> 2, s0 = (tid & 3) * 32;
        bool isL = n < 32;
        int hh = isL ? n : n - 32;
        float bias = isL ? bleft[hh] : bright[hh];
        float scale = isL ? 1.f : (1.f / 128.f);
        __half* dst = (isL ? g_A : g_B) + (size_t)(l * 32 + hh) * 128 + s0;
#pragma unroll
        for (int q = 0; q < 4; q++) {
            float4 v0 = *(float4*)&Osm[n * 132 + s0 + q * 8];
            float4 v1 = *(float4*)&Osm[n * 132 + s0 + q * 8 + 4];
            uint4 pk;
            pk.x = pack2h((v0.x + bias) * scale, (v0.y + bias) * scale);
            pk.y = pack2h((v0.z + bias) * scale, (v0.w + bias) * scale);
            pk.z = pack2h((v1.x + bias) * scale, (v1.y + bias) * scale);
            pk.w = pack2h((v1.z + bias) * scale, (v1.w + bias) * scale);
            *(uint4*)(dst + q * 8) = pk;
        }
    }
}

// ---------------------------------------------------------------------------
// Fused GEMM, fp16 MMA. CTA = 8 l x 8 m = 64 pairs, grid (32,32) = 1024 CTAs
// -> 6.92 waves (98.8% quantization efficiency at 1 CTA/SM).
//   Phase A: D[32 A-rows x 256 m-rows], warp grid 1x8 (warp tile 32x32).
//   Phase B: D[64 pairs x 128 n], warp grid 2x4 (warp tile 32x32).
//   A triple-buffered (32-row chunks), W double-buffered, 2 syncs/ic.
// ---------------------------------------------------------------------------
constexpr int STH   = 136;                      // halves
constexpr int B_OFF = 0;                        // [256][136]  (8m x 32j rows)
constexpr int A_OFF = 256 * STH;                // 3 x [32][136] (8l x 4di)
constexpr int ABUF  = 32 * STH;
constexpr int G_OFF = A_OFF + 3 * ABUF;         // [64][136] pairs x ij
constexpr int W_OFF = G_OFF + 64 * STH;         // 2 x [128][136]
constexpr int WBUF  = 128 * STH;
constexpr int SMEM_FUSED = (W_OFF + 2 * WBUF) * 2;   // 182784 bytes -> 1 CTA/SM

__global__ void __launch_bounds__(256, 1) fused_gemm_kernel(
    const float* __restrict__ pairin,
    const float* __restrict__ bo,
    float* __restrict__ outp)
{
    extern __shared__ __half smh[];
    float* smf = (float*)smh;
    uint32_t sb = smem_u32(smh);
    int tid = threadIdx.x, lane = tid & 31, w = tid >> 5;
    int bl = blockIdx.x, bm = blockIdx.y;

    const __half* gA = g_A + (size_t)(bl * 256) * 128;   // 8 l * 32 i rows
    const __half* gB = g_B + (size_t)(bm * 256) * 128;   // 8 m * 32 j rows

    auto prefetchW = [&](int c) {
        uint32_t base = sb + (uint32_t)((W_OFF + (c & 1) * WBUF) * 2);
        int row = tid >> 1, sg0 = (tid & 1) * 8;
        const __half* src = g_Wt + (size_t)row * 1024 + c * 128 + sg0 * 8;
        uint32_t dst = base + (uint32_t)((row * STH + sg0 * 8) * 2);
#pragma unroll
        for (int sg = 0; sg < 8; sg++) cpa16(dst + sg * 16, src + sg * 8);
    };
    auto prefetchA = [&](int c) {   // A chunk c (32 rows: 8l x 4di) -> slot c%3
        uint32_t base = sb + (uint32_t)((A_OFF + (c % 3) * ABUF) * 2);
#pragma unroll
        for (int it = 0; it < 2; it++) {
            int f = it * 256 + tid;                      // 0..511
            int r = f >> 4, c8 = (f & 15) * 8;           // r = lloc*4+di
            int grow = (r >> 2) * 32 + c * 4 + (r & 3);
            cpa16(base + (uint32_t)((r * STH + c8) * 2),
                  gA + (size_t)grow * 128 + c8);
        }
    };

    // prologue group: B + A0 + A1 + W0
#pragma unroll
    for (int it = 0; it < 16; it++) {
        int f = it * 256 + tid;
        int r = f >> 4, c8 = (f & 15) * 8;
        cpa16(sb + (uint32_t)((B_OFF + r * STH + c8) * 2),
              gB + (size_t)r * 128 + c8);
    }
    prefetchA(0);
    prefetchA(1);
    prefetchW(0);
    cpa_commit();

    float outAcc[2][4][4];
#pragma unroll
    for (int mt = 0; mt < 2; mt++)
#pragma unroll
        for (int nt = 0; nt < 4; nt++)
#pragma unroll
            for (int q = 0; q < 4; q++) outAcc[mt][nt][q] = 0.f;

    // ---- ldmatrix bases ----
    // phase A: M = 32 A-rows (shared across warps), N = warp w's 32 m-rows
    uint32_t aAddrA0 = sb + (uint32_t)((A_OFF + (lane & 15) * STH + (lane >> 4) * 8) * 2);
    uint32_t bAddrA  = sb + (uint32_t)((B_OFF + (w * 32 + ((lane >> 4) & 1) * 8 + (lane & 7)) * STH
                                        + ((lane >> 3) & 1) * 8) * 2);
    // phase B: M = 64 pairs (2 groups of 32), N = 128 n (4 groups of 32)
    int wmB = w >> 2, wnB = w & 3;
    uint32_t aAddrB  = sb + (uint32_t)((G_OFF + (wmB * 32 + (lane & 15)) * STH
                                        + (lane >> 4) * 8) * 2);
    uint32_t bAddrW0 = (uint32_t)((W_OFF + (wnB * 32 + ((lane >> 4) & 1) * 8 + (lane & 7)) * STH
                                   + ((lane >> 3) & 1) * 8) * 2);

    cpa_wait<0>();
    __syncthreads();       // B, A0, A1, W0 visible

#pragma unroll 1
    for (int ic = 0; ic < 8; ic++) {
        if (ic > 0) __syncthreads();     // #1: Gs consumed; A/W slots free
        if (ic < 6) prefetchA(ic + 2);
        if (ic < 7) { prefetchW(ic + 1); cpa_commit(); }

        // ---- phase A: D[32 A-rows x 256 m-rows], K=128 s ----
        uint32_t aA = aAddrA0 + (uint32_t)((ic % 3) * ABUF * 2);
        float accA[2][4][4];
#pragma unroll
        for (int mt = 0; mt < 2; mt++)
#pragma unroll
            for (int nt = 0; nt < 4; nt++)
#pragma unroll
                for (int q = 0; q < 4; q++) accA[mt][nt][q] = 0.f;

#pragma unroll
        for (int ks = 0; ks < 8; ks++) {
            uint32_t a[2][4], b[2][4];
#pragma unroll
            for (int mt = 0; mt < 2; mt++)
                ldsm4(a[mt][0], a[mt][1], a[mt][2], a[mt][3],
                      aA + (uint32_t)((mt * 16 * STH + ks * 16) * 2));
#pragma unroll
            for (int pr = 0; pr < 2; pr++)
                ldsm4(b[pr][0], b[pr][1], b[pr][2], b[pr][3],
                      bAddrA + (uint32_t)((pr * 16 * STH + ks * 16) * 2));
#pragma unroll
            for (int mt = 0; mt < 2; mt++)
#pragma unroll
                for (int nt = 0; nt < 4; nt++)
                    mma16816(accA[mt][nt], a[mt],
                             b[nt >> 1][(nt & 1) * 2], b[nt >> 1][(nt & 1) * 2 + 1]);
        }

        // ---- scatter accA -> Gs[pair][ij_local] (half2 stores) ----
        // D row = A-row (lloc*4+di), D col (warp-local) = j; mloc = w.
        {
            int rq = lane >> 2, cq = (lane & 3) * 2;
#pragma unroll
            for (int mt = 0; mt < 2; mt++) {
#pragma unroll
                for (int nt = 0; nt < 4; nt++) {
                    int jj = nt * 8 + cq;
#pragma unroll
                    for (int rh = 0; rh < 2; rh++) {
                        int r = mt * 16 + rh * 8 + rq;        // lloc*4+di
                        int p = (r >> 2) * 8 + w;
                        int col = (r & 3) * 32 + jj;
                        *(uint32_t*)(smh + G_OFF + p * STH + col) =
                            pack2h(accA[mt][nt][rh * 2], accA[mt][nt][rh * 2 + 1]);
                    }
                }
            }
        }
        if (ic < 7) { cpa_wait<1>(); } else { cpa_wait<0>(); }
        __syncthreads();                 // #2: Gs + W[ic] + A[ic+1] visible

        // ---- phase B: D[64 pairs x 128 n] += Gs @ W[ic]^T ----
        uint32_t sW = sb + bAddrW0 + (uint32_t)((ic & 1) * WBUF * 2);
#pragma unroll
        for (int ks = 0; ks < 8; ks++) {
            uint32_t a[2][4], b[2][4];
#pragma unroll
            for (int mt = 0; mt < 2; mt++)
                ldsm4(a[mt][0], a[mt][1], a[mt][2], a[mt][3],
                      aAddrB + (uint32_t)((mt * 16 * STH + ks * 16) * 2));
#pragma unroll
            for (int pr = 0; pr < 2; pr++)
                ldsm4(b[pr][0], b[pr][1], b[pr][2], b[pr][3],
                      sW + (uint32_t)((pr * 16 * STH + ks * 16) * 2));
#pragma unroll
            for (int mt = 0; mt < 2; mt++)
#pragma unroll
                for (int nt = 0; nt < 4; nt++)
                    mma16816(outAcc[mt][nt], a[mt],
                             b[nt >> 1][(nt & 1) * 2], b[nt >> 1][(nt & 1) * 2 + 1]);
        }
    }
    __syncthreads();

    // ---- epilogue: stage f32 (stride 132), coalesced writes ----
    {
        int rB = lane >> 2, nB = (lane & 3) * 2;
#pragma unroll
        for (int mt = 0; mt < 2; mt++) {
            int p = wmB * 32 + mt * 16 + rB;
#pragma unroll
            for (int nt = 0; nt < 4; nt++) {
                int nc = wnB * 32 + nt * 8 + nB;
                *(float2*)&smf[p * 132 + nc] =
                    make_float2(outAcc[mt][nt][0], outAcc[mt][nt][1]);
                *(float2*)&smf[(p + 8) * 132 + nc] =
                    make_float2(outAcc[mt][nt][2], outAcc[mt][nt][3]);
            }
        }
    }
    __syncthreads();

#pragma unroll
    for (int it = 0; it < 8; it++) {
        int f = it * 256 + tid;          // 2048 float4
        int p = f >> 5;                  // pair 0..63 (= lloc*8+mloc)
        int c4 = (f & 31) * 4;
        int l = bl * 8 + (p >> 3);
        int m = bm * 8 + (p & 7);
        size_t o = ((size_t)(l * L_ + m)) * DP + c4;
        float4 v = *(float4*)&smf[p * 132 + c4];
        float4 pv = *(const float4*)&pairin[o];
        float4 bv = *(const float4*)&bo[c4];
        v.x += pv.x + bv.x; v.y += pv.y + bv.y;
        v.z += pv.z + bv.z; v.w += pv.w + bv.w;
        *(float4*)&outp[o] = v;
    }
}

// ---------------------------------------------------------------------------
// Launch
// ---------------------------------------------------------------------------
extern "C" void kernel_launch(void* const* d_in, const int* in_sizes, int n_in,
                              void* d_out, int out_size)
{
    const float* msa    = (const float*)d_in[0];
    const float* pairin = (const float*)d_in[1];
    const float* gamma  = (const float*)d_in[4];
    const float* beta   = (const float*)d_in[5];
    const float* wl     = (const float*)d_in[6];
    const float* bleft  = (const float*)d_in[7];
    const float* wr     = (const float*)d_in[8];
    const float* bright = (const float*)d_in[9];
    const float* wo     = (const float*)d_in[10];
    const float* bo     = (const float*)d_in[11];
    float* outp = (float*)d_out;

    int smemLn = 192 * XST * 2;   // 101376 bytes
    cudaFuncSetAttribute(ln_proj_kernel,
                         cudaFuncAttributeMaxDynamicSharedMemorySize, smemLn);
    cudaFuncSetAttribute(fused_gemm_kernel,
                         cudaFuncAttributeMaxDynamicSharedMemorySize, SMEM_FUSED);

    ln_proj_kernel<<<256, 256, smemLn>>>(msa, gamma, beta, wl, bleft, wr, bright, wo);
    fused_gemm_kernel<<<dim3(32, 32), 256, SMEM_FUSED>>>(pairin, bo, outp);
}

// round 14
// speedup vs baseline: 1.1661x; 1.1661x over previous
#include <cuda_runtime.h>
#include <cuda_fp16.h>
#include <cstdint>

// Shapes (fixed)
constexpr int N_  = 128;
constexpr int L_  = 256;
constexpr int DM  = 256;
constexpr int DP  = 128;

// Device scratch (fp16)
__device__ __half g_A[8192 * 128];   // [(l*32+i)][s]
__device__ __half g_B[8192 * 128];   // [(m*32+j)][s]
__device__ __half g_Wt[DP * 1024];   // [n][ij]

// ---------------------------------------------------------------------------
// helpers
// ---------------------------------------------------------------------------
__device__ __forceinline__ uint32_t smem_u32(const void* p) {
    uint32_t a;
    asm("{ .reg .u64 t; cvta.to.shared.u64 t, %1; cvt.u32.u64 %0, t; }"
        : "=r"(a) : "l"(p));
    return a;
}
__device__ __forceinline__ void ldsm4(uint32_t& r0, uint32_t& r1,
                                      uint32_t& r2, uint32_t& r3, uint32_t a) {
    asm volatile("ldmatrix.sync.aligned.m8n8.x4.shared.b16 {%0,%1,%2,%3}, [%4];"
                 : "=r"(r0), "=r"(r1), "=r"(r2), "=r"(r3) : "r"(a));
}
__device__ __forceinline__ void mma16816(float* d, const uint32_t* a,
                                         uint32_t b0, uint32_t b1) {
    asm volatile(
        "mma.sync.aligned.m16n8k16.row.col.f32.f16.f16.f32 "
        "{%0,%1,%2,%3}, {%4,%5,%6,%7}, {%8,%9}, {%0,%1,%2,%3};"
        : "+f"(d[0]), "+f"(d[1]), "+f"(d[2]), "+f"(d[3])
        : "r"(a[0]), "r"(a[1]), "r"(a[2]), "r"(a[3]), "r"(b0), "r"(b1));
}
__device__ __forceinline__ void cpa16(uint32_t dst, const void* src) {
    asm volatile("cp.async.cg.shared.global [%0], [%1], 16;"
                 :: "r"(dst), "l"(src) : "memory");
}
__device__ __forceinline__ void cpa_commit() {
    asm volatile("cp.async.commit_group;" ::: "memory");
}
template <int N>
__device__ __forceinline__ void cpa_wait() {
    asm volatile("cp.async.wait_group %0;" :: "n"(N) : "memory");
}
__device__ __forceinline__ uint32_t pack2h(float a, float b) {
    __half2 h = __floats2half2_rn(a, b);
    return *(uint32_t*)&h;
}

// ---------------------------------------------------------------------------
// Kernel 1: LN + projections via tensor cores.
//   Reordered: msa loads issue first; SMEM weight staging overlaps their
//   latency; folded g_Wt transpose moved to the kernel tail.
// ---------------------------------------------------------------------------
constexpr int XST = 264;

__global__ void __launch_bounds__(256) ln_proj_kernel(
    const float* __restrict__ msa,
    const float* __restrict__ gamma,
    const float* __restrict__ beta,
    const float* __restrict__ wl,
    const float* __restrict__ bleft,
    const float* __restrict__ wr,
    const float* __restrict__ bright,
    const float* __restrict__ wo)
{
    extern __shared__ __half sh[];
    __half* Xs = sh;                    // [128][264]
    __half* Wt = sh + 128 * XST;        // [64][264]
    float*  Osm = (float*)sh;           // reuse X region: [64][132]

    int tid = threadIdx.x, lane = tid & 31, w = tid >> 5;
    int l = blockIdx.x;

    float4 ga0 = *(const float4*)&gamma[lane * 8];
    float4 ga1 = *(const float4*)&gamma[lane * 8 + 4];
    float4 be0 = *(const float4*)&beta[lane * 8];
    float4 be1 = *(const float4*)&beta[lane * 8 + 4];

    // ---- LN first: get msa loads into the memory system immediately ----
#pragma unroll 1
    for (int rr4 = 0; rr4 < 4; rr4++) {
        float4 x0[4], x1[4];
#pragma unroll
        for (int r = 0; r < 4; r++) {
            int s = w * 16 + rr4 * 4 + r;
            const float* x = msa + ((size_t)s * L_ + l) * DM;
            x0[r] = *(const float4*)&x[lane * 8];
            x1[r] = *(const float4*)&x[lane * 8 + 4];
        }
#pragma unroll
        for (int r = 0; r < 4; r++) {
            int s = w * 16 + rr4 * 4 + r;
            float sum = x0[r].x + x0[r].y + x0[r].z + x0[r].w
                      + x1[r].x + x1[r].y + x1[r].z + x1[r].w;
            float sq  = x0[r].x*x0[r].x + x0[r].y*x0[r].y + x0[r].z*x0[r].z + x0[r].w*x0[r].w
                      + x1[r].x*x1[r].x + x1[r].y*x1[r].y + x1[r].z*x1[r].z + x1[r].w*x1[r].w;
#pragma unroll
            for (int o = 16; o > 0; o >>= 1) {
                sum += __shfl_xor_sync(0xffffffffu, sum, o);
                sq  += __shfl_xor_sync(0xffffffffu, sq,  o);
            }
            float mu = sum * (1.f / DM);
            float rstd = rsqrtf(sq * (1.f / DM) - mu * mu + 1e-5f);
            uint4 pk;
            pk.x = pack2h((x0[r].x - mu) * rstd * ga0.x + be0.x,
                          (x0[r].y - mu) * rstd * ga0.y + be0.y);
            pk.y = pack2h((x0[r].z - mu) * rstd * ga0.z + be0.z,
                          (x0[r].w - mu) * rstd * ga0.w + be0.w);
            pk.z = pack2h((x1[r].x - mu) * rstd * ga1.x + be1.x,
                          (x1[r].y - mu) * rstd * ga1.y + be1.y);
            pk.w = pack2h((x1[r].z - mu) * rstd * ga1.z + be1.z,
                          (x1[r].w - mu) * rstd * ga1.w + be1.w);
            *(uint4*)&Xs[s * XST + lane * 8] = pk;
        }
    }

    // ---- SMEM weight staging (overlaps msa-load tail) ----
    for (int e = tid; e < 8192; e += 256) {
        int d = e >> 5, h = e & 31;
        Wt[h * XST + d]        = __float2half_rn(wl[e]);
        Wt[(h + 32) * XST + d] = __float2half_rn(wr[e]);
    }
    __syncthreads();

    int wm = w >> 1, wn = w & 1;
    float acc[2][4][4];
#pragma unroll
    for (int mt = 0; mt < 2; mt++)
#pragma unroll
        for (int nt = 0; nt < 4; nt++)
#pragma unroll
            for (int q = 0; q < 4; q++) acc[mt][nt][q] = 0.f;

    uint32_t sb = smem_u32(sh);
    uint32_t aAddr = sb + (uint32_t)(((wm * 32 + (lane & 15)) * XST + (lane >> 4) * 8) * 2);
    uint32_t bAddr = sb + (uint32_t)((128 * XST
                    + (wn * 32 + ((lane >> 4) & 1) * 8 + (lane & 7)) * XST
                    + ((lane >> 3) & 1) * 8) * 2);

#pragma unroll
    for (int ks = 0; ks < 16; ks++) {
        uint32_t a[2][4], b[2][4];
#pragma unroll
        for (int mt = 0; mt < 2; mt++)
            ldsm4(a[mt][0], a[mt][1], a[mt][2], a[mt][3],
                  aAddr + (uint32_t)((mt * 16 * XST + ks * 16) * 2));
#pragma unroll
        for (int n2 = 0; n2 < 2; n2++)
            ldsm4(b[n2][0], b[n2][1], b[n2][2], b[n2][3],
                  bAddr + (uint32_t)((n2 * 16 * XST + ks * 16) * 2));
#pragma unroll
        for (int mt = 0; mt < 2; mt++)
#pragma unroll
            for (int nt = 0; nt < 4; nt++)
                mma16816(acc[mt][nt], a[mt],
                         b[nt >> 1][(nt & 1) * 2], b[nt >> 1][(nt & 1) * 2 + 1]);
    }
    __syncthreads();

    {
        int rB = lane >> 2, cB = (lane & 3) * 2;
#pragma unroll
        for (int mt = 0; mt < 2; mt++) {
            int r = wm * 32 + mt * 16 + rB;
#pragma unroll
            for (int nt = 0; nt < 4; nt++) {
                int c = wn * 32 + nt * 8 + cB;
                Osm[c * 132 + r]            = acc[mt][nt][0];
                Osm[(c + 1) * 132 + r]      = acc[mt][nt][1];
                Osm[c * 132 + r + 8]        = acc[mt][nt][2];
                Osm[(c + 1) * 132 + r + 8]  = acc[mt][nt][3];
            }
        }
    }
    __syncthreads();

    {
        int n = tid >> 2, s0 = (tid & 3) * 32;
        bool isL = n < 32;
        int hh = isL ? n : n - 32;
        float bias = isL ? bleft[hh] : bright[hh];
        float scale = isL ? 1.f : (1.f / 128.f);
        __half* dst = (isL ? g_A : g_B) + (size_t)(l * 32 + hh) * 128 + s0;
#pragma unroll
        for (int q = 0; q < 4; q++) {
            float4 v0 = *(float4*)&Osm[n * 132 + s0 + q * 8];
            float4 v1 = *(float4*)&Osm[n * 132 + s0 + q * 8 + 4];
            uint4 pk;
            pk.x = pack2h((v0.x + bias) * scale, (v0.y + bias) * scale);
            pk.y = pack2h((v0.z + bias) * scale, (v0.w + bias) * scale);
            pk.z = pack2h((v1.x + bias) * scale, (v1.y + bias) * scale);
            pk.w = pack2h((v1.z + bias) * scale, (v1.w + bias) * scale);
            *(uint4*)(dst + q * 8) = pk;
        }
    }

    // ---- folded g_Wt transpose at the tail (fire-and-forget stores) ----
#pragma unroll
    for (int it = 0; it < 2; it++) {
        int idx = blockIdx.x * 512 + it * 256 + tid;
        int k = idx >> 7, n = idx & 127;
        g_Wt[(size_t)n * 1024 + k] = __float2half_rn(wo[idx]);
    }
}

// ---------------------------------------------------------------------------
// Fused GEMM (round-12 winner, byte-identical). CTA = 16 l x 8 m, grid (16,32).
// ---------------------------------------------------------------------------
constexpr int STH   = 136;                      // halves
constexpr int B_OFF = 0;                        // [256][136]  (8m x 32j rows)
constexpr int A_OFF = 256 * STH;                // 3 x [64][136] (16l x 4di)
constexpr int ABUF  = 64 * STH;
constexpr int G_OFF = A_OFF + 3 * ABUF;         // [128][136] pairs x ij
constexpr int W_OFF = G_OFF + 128 * STH;        // 2 x [128][136]
constexpr int WBUF  = 128 * STH;
constexpr int SMEM_FUSED = (W_OFF + 2 * WBUF) * 2;   // 226304 bytes

__global__ void __launch_bounds__(256, 1) fused_gemm_kernel(
    const float* __restrict__ pairin,
    const float* __restrict__ bo,
    float* __restrict__ outp)
{
    extern __shared__ __half smh[];
    float* smf = (float*)smh;
    uint32_t sb = smem_u32(smh);
    int tid = threadIdx.x, lane = tid & 31, w = tid >> 5;
    int bl = blockIdx.x, bm = blockIdx.y;

    const __half* gA = g_A + (size_t)(bl * 512) * 128;
    const __half* gB = g_B + (size_t)(bm * 256) * 128;

    auto prefetchW = [&](int c) {
        uint32_t base = sb + (uint32_t)((W_OFF + (c & 1) * WBUF) * 2);
        int row = tid >> 1, sg0 = (tid & 1) * 8;
        const __half* src = g_Wt + (size_t)row * 1024 + c * 128 + sg0 * 8;
        uint32_t dst = base + (uint32_t)((row * STH + sg0 * 8) * 2);
#pragma unroll
        for (int sg = 0; sg < 8; sg++) cpa16(dst + sg * 16, src + sg * 8);
    };
    auto prefetchA = [&](int c) {
        uint32_t base = sb + (uint32_t)((A_OFF + (c % 3) * ABUF) * 2);
#pragma unroll
        for (int it = 0; it < 4; it++) {
            int f = it * 256 + tid;
            int r = f >> 4, c8 = (f & 15) * 8;
            int grow = (r >> 2) * 32 + c * 4 + (r & 3);
            cpa16(base + (uint32_t)((r * STH + c8) * 2),
                  gA + (size_t)grow * 128 + c8);
        }
    };

#pragma unroll
    for (int it = 0; it < 16; it++) {
        int f = it * 256 + tid;
        int r = f >> 4, c8 = (f & 15) * 8;
        cpa16(sb + (uint32_t)((B_OFF + r * STH + c8) * 2),
              gB + (size_t)r * 128 + c8);
    }
    prefetchA(0);
    prefetchA(1);
    prefetchW(0);
    cpa_commit();

    float outAcc[4][4][4];
#pragma unroll
    for (int mt = 0; mt < 4; mt++)
#pragma unroll
        for (int nt = 0; nt < 4; nt++)
#pragma unroll
            for (int q = 0; q < 4; q++) outAcc[mt][nt][q] = 0.f;

    int wm2 = w >> 2;
    int wn4 = w & 3;
    int wmB = w >> 2, wnB = w & 3;

    uint32_t aAddrA0 = sb + (uint32_t)((A_OFF + (wm2 * 32 + (lane & 15)) * STH
                                        + (lane >> 4) * 8) * 2);
    uint32_t bAddrA  = sb + (uint32_t)((B_OFF + (wn4 * 64 + ((lane >> 4) & 1) * 8 + (lane & 7)) * STH
                                        + ((lane >> 3) & 1) * 8) * 2);
    uint32_t aAddrB  = sb + (uint32_t)((G_OFF + (wmB * 64 + (lane & 15)) * STH
                                        + (lane >> 4) * 8) * 2);
    uint32_t bAddrW0 = (uint32_t)((W_OFF + (wnB * 32 + ((lane >> 4) & 1) * 8 + (lane & 7)) * STH
                                   + ((lane >> 3) & 1) * 8) * 2);

    cpa_wait<0>();
    __syncthreads();

#pragma unroll 1
    for (int ic = 0; ic < 8; ic++) {
        if (ic > 0) __syncthreads();
        if (ic < 6) prefetchA(ic + 2);
        if (ic < 7) { prefetchW(ic + 1); cpa_commit(); }

        uint32_t aA = aAddrA0 + (uint32_t)((ic % 3) * ABUF * 2);
        float accA[2][8][4];
#pragma unroll
        for (int mt = 0; mt < 2; mt++)
#pragma unroll
            for (int nt = 0; nt < 8; nt++)
#pragma unroll
                for (int q = 0; q < 4; q++) accA[mt][nt][q] = 0.f;

#pragma unroll
        for (int ks = 0; ks < 8; ks++) {
            uint32_t a[2][4], b[4][4];
#pragma unroll
            for (int mt = 0; mt < 2; mt++)
                ldsm4(a[mt][0], a[mt][1], a[mt][2], a[mt][3],
                      aA + (uint32_t)((mt * 16 * STH + ks * 16) * 2));
#pragma unroll
            for (int pr = 0; pr < 4; pr++)
                ldsm4(b[pr][0], b[pr][1], b[pr][2], b[pr][3],
                      bAddrA + (uint32_t)((pr * 16 * STH + ks * 16) * 2));
#pragma unroll
            for (int mt = 0; mt < 2; mt++)
#pragma unroll
                for (int nt = 0; nt < 8; nt++)
                    mma16816(accA[mt][nt], a[mt],
                             b[nt >> 1][(nt & 1) * 2], b[nt >> 1][(nt & 1) * 2 + 1]);
        }

        {
            int rq = lane >> 2, cq = (lane & 3) * 2;
#pragma unroll
            for (int mt = 0; mt < 2; mt++) {
#pragma unroll
                for (int nt = 0; nt < 8; nt++) {
                    int cc = wn4 * 64 + nt * 8 + cq;
                    int mloc = cc >> 5, jj = cc & 31;
#pragma unroll
                    for (int rh = 0; rh < 2; rh++) {
                        int r = wm2 * 32 + mt * 16 + rh * 8 + rq;
                        int p = (r >> 2) * 8 + mloc;
                        int col = (r & 3) * 32 + jj;
                        *(uint32_t*)(smh + G_OFF + p * STH + col) =
                            pack2h(accA[mt][nt][rh * 2], accA[mt][nt][rh * 2 + 1]);
                    }
                }
            }
        }
        if (ic < 7) { cpa_wait<1>(); } else { cpa_wait<0>(); }
        __syncthreads();

        uint32_t sW = sb + bAddrW0 + (uint32_t)((ic & 1) * WBUF * 2);
#pragma unroll
        for (int ks = 0; ks < 8; ks++) {
            uint32_t a[4][4], b[2][4];
#pragma unroll
            for (int mt = 0; mt < 4; mt++)
                ldsm4(a[mt][0], a[mt][1], a[mt][2], a[mt][3],
                      aAddrB + (uint32_t)((mt * 16 * STH + ks * 16) * 2));
#pragma unroll
            for (int pr = 0; pr < 2; pr++)
                ldsm4(b[pr][0], b[pr][1], b[pr][2], b[pr][3],
                      sW + (uint32_t)((pr * 16 * STH + ks * 16) * 2));
#pragma unroll
            for (int mt = 0; mt < 4; mt++)
#pragma unroll
                for (int nt = 0; nt < 4; nt++)
                    mma16816(outAcc[mt][nt], a[mt],
                             b[nt >> 1][(nt & 1) * 2], b[nt >> 1][(nt & 1) * 2 + 1]);
        }
    }
    __syncthreads();

    {
        int rB = lane >> 2, nB = (lane & 3) * 2;
#pragma unroll
        for (int mt = 0; mt < 4; mt++) {
            int p = wmB * 64 + mt * 16 + rB;
#pragma unroll
            for (int nt = 0; nt < 4; nt++) {
                int nc = wnB * 32 + nt * 8 + nB;
                *(float2*)&smf[p * 132 + nc] =
                    make_float2(outAcc[mt][nt][0], outAcc[mt][nt][1]);
                *(float2*)&smf[(p + 8) * 132 + nc] =
                    make_float2(outAcc[mt][nt][2], outAcc[mt][nt][3]);
            }
        }
    }
    __syncthreads();

#pragma unroll
    for (int it = 0; it < 16; it++) {
        int f = it * 256 + tid;
        int p = f >> 5;
        int c4 = (f & 31) * 4;
        int l = bl * 16 + (p >> 3);
        int m = bm * 8 + (p & 7);
        size_t o = ((size_t)(l * L_ + m)) * DP + c4;
        float4 v = *(float4*)&smf[p * 132 + c4];
        float4 pv = *(const float4*)&pairin[o];
        float4 bv = *(const float4*)&bo[c4];
        v.x += pv.x + bv.x; v.y += pv.y + bv.y;
        v.z += pv.z + bv.z; v.w += pv.w + bv.w;
        *(float4*)&outp[o] = v;
    }
}

// ---------------------------------------------------------------------------
// Launch
// ---------------------------------------------------------------------------
extern "C" void kernel_launch(void* const* d_in, const int* in_sizes, int n_in,
                              void* d_out, int out_size)
{
    const float* msa    = (const float*)d_in[0];
    const float* pairin = (const float*)d_in[1];
    const float* gamma  = (const float*)d_in[4];
    const float* beta   = (const float*)d_in[5];
    const float* wl     = (const float*)d_in[6];
    const float* bleft  = (const float*)d_in[7];
    const float* wr     = (const float*)d_in[8];
    const float* bright = (const float*)d_in[9];
    const float* wo     = (const float*)d_in[10];
    const float* bo     = (const float*)d_in[11];
    float* outp = (float*)d_out;

    int smemLn = 192 * XST * 2;   // 101376 bytes
    cudaFuncSetAttribute(ln_proj_kernel,
                         cudaFuncAttributeMaxDynamicSharedMemorySize, smemLn);
    cudaFuncSetAttribute(fused_gemm_kernel,
                         cudaFuncAttributeMaxDynamicSharedMemorySize, SMEM_FUSED);

    ln_proj_kernel<<<256, 256, smemLn>>>(msa, gamma, beta, wl, bleft, wr, bright, wo);
    fused_gemm_kernel<<<dim3(16, 32), 256, SMEM_FUSED>>>(pairin, bo, outp);
}